// round 17
// baseline (speedup 1.0000x reference)
#include <cuda_runtime.h>
#include <cuda_bf16.h>

// Problem shape (fixed by the dataset)
#define N_DIM 8
#define V_DIM 3
#define C_DIM 24
#define T_DIM 8
#define H_DIM 128
#define W_DIM 128

constexpr int HW      = H_DIM * W_DIM;         // 16384
constexpr int VCT     = V_DIM * C_DIM * T_DIM; // 576 slabs per n
constexpr int CHUNK   = 2048;                  // hw positions per block
constexpr int NCHUNK  = HW / CHUNK;            // 8
constexpr int GROUP   = 48;                    // slabs per block (6 c x 8 t)
constexpr int NGROUP  = VCT / GROUP;           // 12
constexpr int MAIN_BLOCKS = N_DIM * NCHUNK * NGROUP;  // 768 (<= 8/SM * 148: ONE wave)
constexpr int THREADS = 256;
constexpr int F4_PER_THREAD = CHUNK / 4 / THREADS;    // 2

// Deterministic reduction scratch (static device globals — no allocation)
__device__ float g_part[MAIN_BLOCKS];
__device__ float g_maskchunk[N_DIM * NCHUNK];   // per-(n,chunk) integer mask sums (exact)
__device__ unsigned int g_count = 0;            // completion counter (reset by finisher)

// st.global.cg — write straight to L2
__device__ __forceinline__ void stcg(float* p, float v) {
    asm volatile("st.global.cg.f32 [%0], %1;" :: "l"(p), "f"(v) : "memory");
}
__device__ __forceinline__ float ldcg(const float* p) {
    float v;
    asm volatile("ld.global.cg.f32 %0, [%1];" : "=f"(v) : "l"(p) : "memory");
    return v;
}
// acq_rel gpu-scope atomic add (sem/scope BEFORE space per PTX grammar).
// Release orders our prior partial store; acquire orders the finisher's loads.
__device__ __forceinline__ unsigned int atomic_add_acqrel(unsigned int* p, unsigned int v) {
    unsigned int old;
    asm volatile("atom.acq_rel.gpu.global.add.u32 %0, [%1], %2;"
                 : "=r"(old) : "l"(p), "r"(v) : "memory");
    return old;
}

__global__ __launch_bounds__(THREADS, 8)     // 32-reg budget → 8 blocks/SM, 64 warps
void anomaly_l1_fused(const float* __restrict__ pred,
                      const int*   __restrict__ mask,
                      const float* __restrict__ vq0,
                      float* __restrict__ out)
{
    __shared__ float sw[CHUNK];            // weights (1 - mask) for this hw-chunk
    __shared__ float sred[THREADS / 32];
    __shared__ unsigned int s_isLast;

    const int b   = blockIdx.x;
    const int tid = threadIdx.x;

    // ---- decode (n, chunk, group) ----
    const int group = b % NGROUP;                  // 0..11
    const int chunk = (b / NGROUP) % NCHUNK;       // 0..7
    const int n     = b / (NGROUP * NCHUNK);       // 0..7

    // Stage weights into SMEM once; reused across GROUP=48 slabs (R1 form:
    // keeps the hot loop at ~32 regs → 8 blocks/SM occupancy).
    int msum_local = 0;
    {
        const int4* m4 = reinterpret_cast<const int4*>(mask + n * HW + chunk * CHUNK);
        #pragma unroll
        for (int k = 0; k < F4_PER_THREAD; ++k) {
            int4 v = m4[tid + k * THREADS];
            msum_local += v.x + v.y + v.z + v.w;
            float4 w = make_float4(1.f - (float)v.x, 1.f - (float)v.y,
                                   1.f - (float)v.z, 1.f - (float)v.w);
            reinterpret_cast<float4*>(sw)[tid + k * THREADS] = w;
        }
    }

    // group==0 blocks record their (n,chunk) mask sum (integer: exact denominator).
    if (group == 0) {
        int s = msum_local;
        #pragma unroll
        for (int o = 16; o; o >>= 1) s += __shfl_xor_sync(0xFFFFFFFFu, s, o);
        if ((tid & 31) == 0) sred[tid >> 5] = (float)s;
        __syncthreads();
        if (tid == 0) {
            float t = 0.f;
            #pragma unroll
            for (int i = 0; i < THREADS / 32; ++i) t += sred[i];  // ints <= 2048: exact
            stcg(&g_maskchunk[n * NCHUNK + chunk], t);
        }
    }
    __syncthreads();   // sw visible (and sred reusable)

    // Slabs group*48 .. group*48+47: c = (group%4)*6 + (s>>3), t = low 3 bits.
    const int c0 = (group & 3) * 6;
    const float* base = pred + ((size_t)n * VCT + (size_t)group * GROUP) * (size_t)HW
                             + (size_t)chunk * CHUNK;

    float acc = 0.f;
    #pragma unroll 4
    for (int s = 0; s < GROUP; ++s) {
        const float vq = __ldg(vq0 + c0 + (s >> 3));   // L1-resident
        const float4* p = reinterpret_cast<const float4*>(base + (size_t)s * HW);
        #pragma unroll
        for (int k = 0; k < F4_PER_THREAD; ++k) {
            float4 x = p[tid + k * THREADS];
            float4 w = reinterpret_cast<const float4*>(sw)[tid + k * THREADS];
            acc = fmaf(fabsf(x.x - vq), w.x, acc);
            acc = fmaf(fabsf(x.y - vq), w.y, acc);
            acc = fmaf(fabsf(x.z - vq), w.z, acc);
            acc = fmaf(fabsf(x.w - vq), w.w, acc);
        }
    }

    #pragma unroll
    for (int o = 16; o; o >>= 1) acc += __shfl_xor_sync(0xFFFFFFFFu, acc, o);
    if ((tid & 31) == 0) sred[tid >> 5] = acc;
    __syncthreads();
    if (tid == 0) {
        float t = 0.f;
        #pragma unroll
        for (int i = 0; i < THREADS / 32; ++i) t += sred[i];
        stcg(&g_part[b], t);
        // Release-ordered completion mark (elects the finisher).
        unsigned int prev = atomic_add_acqrel(&g_count, 1u);
        s_isLast = (prev == MAIN_BLOCKS - 1u) ? 1u : 0u;
    }
    __syncthreads();

    // ---- last-block-finishes: deterministic final reduction ----
    // Summation walks g_part[] in fixed index order → bit-deterministic.
    if (s_isLast) {
        float a = 0.f;
        #pragma unroll 1
        for (int i = tid; i < MAIN_BLOCKS; i += THREADS) a += ldcg(&g_part[i]);
        #pragma unroll
        for (int o = 16; o; o >>= 1) a += __shfl_xor_sync(0xFFFFFFFFu, a, o);
        if ((tid & 31) == 0) sred[tid >> 5] = a;
        __syncthreads();
        if (tid == 0) {
            float num = 0.f;
            #pragma unroll
            for (int i = 0; i < THREADS / 32; ++i) num += sred[i];
            float msum = 0.f;
            #pragma unroll
            for (int i = 0; i < N_DIM * NCHUNK; ++i) msum += ldcg(&g_maskchunk[i]);
            double sumw = (double)N_DIM * HW - (double)msum;  // sum of weights over (N,H,W)
            double den  = sumw * (double)VCT;
            out[0] = (float)((double)num / den);
            g_count = 0;   // reset for next graph replay
        }
    }
}

extern "C" void kernel_launch(void* const* d_in, const int* in_sizes, int n_in,
                              void* d_out, int out_size)
{
    const float* pred = (const float*)d_in[0];   // (N,V,C,T,H,W) fp32
    const int*   mask = (const int*)  d_in[1];   // (N,H,W) int32
    const float* vq0  = (const float*)d_in[2];   // (1,C) fp32
    float* out = (float*)d_out;

    anomaly_l1_fused<<<MAIN_BLOCKS, THREADS>>>(pred, mask, vq0, out);
}